// round 1
// baseline (speedup 1.0000x reference)
#include <cuda_runtime.h>
#include <math.h>

#define BATCH 8
#define DET   512
#define NANG  180
#define PADW  768
#define POFF  128

// G2[k] = g[|k-512|] : doubled/shifted ramp-filter spatial kernel so the
// filter inner loop indexes with a monotone (base - j) address, no abs().
__device__ float g_filt2[1024];
// Filtered projections, transposed to [b][a][d] and zero-padded:
// index (b*NANG + a)*PADW + POFF + d.  Pad absorbs all out-of-range lerp taps.
__device__ float g_scratch[BATCH * NANG * PADW];

__global__ void init_g_kernel() {
    int k = blockIdx.x * blockDim.x + threadIdx.x;
    if (k >= 1024) return;
    int m = k - 512; if (m < 0) m = -m;
    float v = 0.0f;
    if (m == 0) v = 0.5f;
    else if (m & 1) {
        double pm = 3.141592653589793 * (double)m;
        v = (float)(-2.0 / (pm * pm));
    }
    g_filt2[k] = v;
}

__global__ void zero_scratch_kernel() {
    int i = blockIdx.x * blockDim.x + threadIdx.x;
    if (i < BATCH * NANG * PADW) g_scratch[i] = 0.0f;
}

// Ramp filter as symmetric Toeplitz matvec with parity split (even-|m| taps
// are zero except m=0).  Block = (d-chunk of 8, batch); thread = angle.
// x layout: [b][d][a] (a contiguous -> coalesced loads across threads).
__global__ void __launch_bounds__(192) filt_kernel(const float* __restrict__ x) {
    __shared__ float gs[1024];
    for (int i = threadIdx.x; i < 1024; i += 192) gs[i] = g_filt2[i];
    __syncthreads();

    int b = blockIdx.y;
    int dbase = blockIdx.x * 8;        // always even
    int a = threadIdx.x;
    if (a >= NANG) return;

    const float* xb = x + (size_t)b * DET * NANG + a;

    float acc0, acc1, acc2, acc3, acc4, acc5, acc6, acc7;
    // m = 0 term: g[0] = 0.5
    acc0 = 0.5f * xb[(dbase + 0) * NANG];
    acc1 = 0.5f * xb[(dbase + 1) * NANG];
    acc2 = 0.5f * xb[(dbase + 2) * NANG];
    acc3 = 0.5f * xb[(dbase + 3) * NANG];
    acc4 = 0.5f * xb[(dbase + 4) * NANG];
    acc5 = 0.5f * xb[(dbase + 5) * NANG];
    acc6 = 0.5f * xb[(dbase + 6) * NANG];
    acc7 = 0.5f * xb[(dbase + 7) * NANG];

    // G2 index for accumulator i at column j:  512 + dbase + i - j.
    // Even j feeds odd-i accumulators (|d-j| odd), odd j feeds even-i ones.
    // g0[i] (i odd, col je) and g0[i-1+? ] share elements: only 5 distinct
    // shared loads per j-pair: g0[-1], g0[1], g0[3], g0[5], g0[7].
    const float* gp = gs + 512 + dbase;
    const float* xr = xb;

    #pragma unroll 4
    for (int j = 0; j < DET; j += 2) {
        float xe = xr[0];          // x[b][j][a]
        float xo = xr[NANG];       // x[b][j+1][a]
        xr += 2 * NANG;
        const float* g0 = gp - j;
        float gm1 = g0[-1], g1 = g0[1], g3 = g0[3], g5 = g0[5], g7 = g0[7];
        // odd d (odd i) with even j
        acc1 = fmaf(g1, xe, acc1);
        acc3 = fmaf(g3, xe, acc3);
        acc5 = fmaf(g5, xe, acc5);
        acc7 = fmaf(g7, xe, acc7);
        // even d (even i) with odd j: index i-1
        acc0 = fmaf(gm1, xo, acc0);
        acc2 = fmaf(g1,  xo, acc2);
        acc4 = fmaf(g3,  xo, acc4);
        acc6 = fmaf(g5,  xo, acc6);
    }

    float* out = g_scratch + ((size_t)b * NANG + a) * PADW + POFF + dbase;
    out[0] = acc0; out[1] = acc1; out[2] = acc2; out[3] = acc3;
    out[4] = acc4; out[5] = acc5; out[6] = acc6; out[7] = acc7;
}

// Backprojection: 2 pixels per thread (iy, iy+8), padded lerp (no predicates).
__global__ void __launch_bounds__(256) bp_kernel(float* __restrict__ out) {
    __shared__ float2 cs[NANG];
    int tid = threadIdx.y * 32 + threadIdx.x;
    if (tid < NANG) {
        float th = (float)tid * 0.017453292519943295f;
        float s, c;
        sincosf(th, &s, &c);
        cs[tid] = make_float2(c * 255.5f, s * 255.5f);
    }
    __syncthreads();

    int b   = blockIdx.z;
    int ix  = blockIdx.x * 32 + threadIdx.x;
    int iy0 = blockIdx.y * 16 + threadIdx.y;
    int iy1 = iy0 + 8;

    const float step = 2.0f / 511.0f;
    // no-FMA grid coords to track jnp.linspace rounding (mask sensitivity)
    float ux  = __fadd_rn(__fmul_rn((float)ix,  step), -1.0f);
    float uy0 = __fadd_rn(__fmul_rn((float)iy0, step), -1.0f);
    float uy1 = __fadd_rn(__fmul_rn((float)iy1, step), -1.0f);

    const float* p = g_scratch + (size_t)b * NANG * PADW + POFF;

    float acc0 = 0.0f, acc1 = 0.0f;
    #pragma unroll 4
    for (int a = 0; a < NANG; a++, p += PADW) {
        float2 t = cs[a];
        float yi0 = fmaf(ux, t.x, fmaf(-uy0, t.y, 255.5f));
        float yi1 = fmaf(ux, t.x, fmaf(-uy1, t.y, 255.5f));

        float f0 = floorf(yi0);
        float f1 = floorf(yi1);
        int   i0 = (int)f0;
        int   i1 = (int)f1;
        float w0 = yi0 - f0;
        float w1 = yi1 - f1;

        float v00 = p[i0], v01 = p[i0 + 1];
        float v10 = p[i1], v11 = p[i1 + 1];
        acc0 += fmaf(w0, v01 - v00, v00);
        acc1 += fmaf(w1, v11 - v10, v10);
    }

    const float scale = 0.008726646259971648f;  // pi/360
    float r20 = __fadd_rn(__fmul_rn(ux, ux), __fmul_rn(uy0, uy0));
    float r21 = __fadd_rn(__fmul_rn(ux, ux), __fmul_rn(uy1, uy1));
    float res0 = (r20 <= 1.0f) ? acc0 * scale : 0.0f;
    float res1 = (r21 <= 1.0f) ? acc1 * scale : 0.0f;

    out[((size_t)b * 512 + iy0) * 512 + ix] = res0;
    out[((size_t)b * 512 + iy1) * 512 + ix] = res1;
}

extern "C" void kernel_launch(void* const* d_in, const int* in_sizes, int n_in,
                              void* d_out, int out_size) {
    const float* x = (const float*)d_in[0];
    float* out = (float*)d_out;

    init_g_kernel<<<2, 512>>>();
    zero_scratch_kernel<<<(BATCH * NANG * PADW + 255) / 256, 256>>>();
    filt_kernel<<<dim3(DET / 8, BATCH), 192>>>(x);
    bp_kernel<<<dim3(512 / 32, 512 / 16, BATCH), dim3(32, 8)>>>(out);
}